// round 3
// baseline (speedup 1.0000x reference)
#include <cuda_runtime.h>

// Rotated ROI cropper, channel-packed smem staging:
//   x:     [8, 3, 1024, 1024] fp32
//   boxes: [8, 64, 5] fp32  (cx, cy, w, h, angle_deg)
//   out:   [512, 3, 48, 320] fp32
//
// Block = one 32x16 output tile of one box. Source bbox of the tile is <= 38px
// per side; staged in smem as float4 (c0,c1,c2,pad) so each bilinear tap is a
// single LDS.128. Each thread computes an x-pair (2 adjacent output px) and
// stores float2 per channel.

#define IMG_H 1024
#define IMG_W 1024
#define OUT_H 48
#define OUT_W 320
#define CHANS 3
#define N_BOXES_TOTAL 512
#define PLANE (IMG_H * IMG_W)

#define TILE_OX 32
#define TILE_OY 16
#define NTX (OUT_W / TILE_OX)   // 10
#define NTY (OUT_H / TILE_OY)   // 3

#define STILE  38
#define SPITCH 39               // odd pitch -> bank spread on diagonals

#define NTHREADS 256

__global__ __launch_bounds__(NTHREADS)
void rotated_roi_crop_v3(const float* __restrict__ x,
                         const float* __restrict__ boxes,
                         float* __restrict__ out) {
    __shared__ float4 tile[STILE][SPITCH];  // (c0, c1, c2, pad)

    const int bid     = blockIdx.x;
    const int tx_tile = bid % NTX;
    const int ty_tile = (bid / NTX) % NTY;
    const int g       = bid / (NTX * NTY);

    // ---- box params (uniform broadcast) ----
    const float* bp = boxes + g * 5;
    const float cx  = bp[0];
    const float cy  = bp[1];
    const float bw  = bp[2];
    const float bh  = bp[3];
    const float ang = bp[4];

    const float theta = -ang * 0.017453292519943295f;
    float s_, c_;
    sincosf(theta, &s_, &c_);
    const float b = c_ * 0.5f;
    const float a = s_ * 0.5f;

    const float p0x = cx - a * bh - b * bw;
    const float p0y = cy + b * bh - a * bw;
    const float p1x = cx + a * bh - b * bw;
    const float p1y = cy - b * bh - a * bw;
    const float p2x = 2.0f * cx - p0x;
    const float p2y = 2.0f * cy - p0y;

    const float ex_x = p2x - p1x;   // source delta per unit u
    const float ex_y = p2y - p1y;
    const float ey_x = p0x - p1x;   // source delta per unit v
    const float ey_y = p0y - p1y;

    // ---- source bbox of this tile (4 affine corners) ----
    const float u0 = (float)(tx_tile * TILE_OX)               / (float)OUT_W;
    const float u1 = (float)(tx_tile * TILE_OX + TILE_OX - 1) / (float)OUT_W;
    const float v0 = (float)(ty_tile * TILE_OY)               / (float)OUT_H;
    const float v1 = (float)(ty_tile * TILE_OY + TILE_OY - 1) / (float)OUT_H;

    const float sxa = p1x + u0 * ex_x + v0 * ey_x;
    const float sxb = p1x + u1 * ex_x + v0 * ey_x;
    const float sxc = p1x + u0 * ex_x + v1 * ey_x;
    const float sxd = p1x + u1 * ex_x + v1 * ey_x;
    const float sya = p1y + u0 * ex_y + v0 * ey_y;
    const float syb = p1y + u1 * ex_y + v0 * ey_y;
    const float syc = p1y + u0 * ex_y + v1 * ey_y;
    const float syd = p1y + u1 * ex_y + v1 * ey_y;

    const int x_org = (int)floorf(fminf(fminf(sxa, sxb), fminf(sxc, sxd)));
    const int y_org = (int)floorf(fminf(fminf(sya, syb), fminf(syc, syd)));
    const int bwid = min((int)floorf(fmaxf(fmaxf(sxa, sxb), fmaxf(sxc, sxd))) + 2 - x_org, STILE);
    const int bhei = min((int)floorf(fmaxf(fmaxf(sya, syb), fmaxf(syc, syd))) + 2 - y_org, STILE);

    // ---- staged load: warp-row-strided, no division ----
    const int lane = threadIdx.x & 31;
    const int wrp  = threadIdx.x >> 5;   // 0..7

    const int batch = g >> 6;
    const float* img = x + (size_t)batch * CHANS * PLANE;
    const bool wide = (bwid > 32);

    for (int yy = wrp; yy < bhei; yy += 8) {
        const int gy = y_org + yy;
        const bool rok = ((unsigned)gy < IMG_H);
        const float* rp = img + (size_t)gy * IMG_W;

        {
            const int xx = lane;
            const int gx = x_org + xx;
            const bool ok = rok & ((unsigned)gx < IMG_W) & (xx < bwid);
            float4 t = make_float4(0.f, 0.f, 0.f, 0.f);
            if (ok) {
                t.x = __ldg(rp + gx);
                t.y = __ldg(rp + gx + PLANE);
                t.z = __ldg(rp + gx + 2 * PLANE);
            }
            tile[yy][xx] = t;
        }
        if (wide) {
            const int xx = 32 + lane;
            if (xx < STILE) {
                const int gx = x_org + xx;
                const bool ok = rok & ((unsigned)gx < IMG_W) & (xx < bwid);
                float4 t = make_float4(0.f, 0.f, 0.f, 0.f);
                if (ok) {
                    t.x = __ldg(rp + gx);
                    t.y = __ldg(rp + gx + PLANE);
                    t.z = __ldg(rp + gx + 2 * PLANE);
                }
                tile[yy][xx] = t;
            }
        }
    }
    __syncthreads();

    // ---- compute: thread = x-pair within one row; 2 px; float2 stores ----
    const int xp = (lane & 15) * 2;            // 0,2,...,30
    const int rh = lane >> 4;                  // 0/1
    const int oy = ty_tile * TILE_OY + wrp * 2 + rh;
    const int ox = tx_tile * TILE_OX + xp;

    const float du_x = ex_x * (1.0f / OUT_W);
    const float du_y = ex_y * (1.0f / OUT_W);

    const float u = (float)ox / (float)OUT_W;
    const float v = (float)oy / (float)OUT_H;

    const float sx0 = p1x + u * ex_x + v * ey_x;
    const float sy0 = p1y + u * ex_y + v * ey_y;
    const float sx1 = sx0 + du_x;
    const float sy1 = sy0 + du_y;

    float r0[CHANS], r1[CHANS];

    // pixel A
    {
        const float x0f = floorf(sx0);
        const float y0f = floorf(sy0);
        const float dx = sx0 - x0f;
        const float dy = sy0 - y0f;
        int lx = min(max((int)x0f - x_org, 0), bwid - 2);
        int ly = min(max((int)y0f - y_org, 0), bhei - 2);
        const float w00 = (1.0f - dx) * (1.0f - dy);
        const float w10 = dx * (1.0f - dy);
        const float w01 = (1.0f - dx) * dy;
        const float w11 = dx * dy;
        const float4 t00 = tile[ly][lx];
        const float4 t10 = tile[ly][lx + 1];
        const float4 t01 = tile[ly + 1][lx];
        const float4 t11 = tile[ly + 1][lx + 1];
        r0[0] = t00.x * w00 + t10.x * w10 + t01.x * w01 + t11.x * w11;
        r0[1] = t00.y * w00 + t10.y * w10 + t01.y * w01 + t11.y * w11;
        r0[2] = t00.z * w00 + t10.z * w10 + t01.z * w01 + t11.z * w11;
    }
    // pixel B
    {
        const float x0f = floorf(sx1);
        const float y0f = floorf(sy1);
        const float dx = sx1 - x0f;
        const float dy = sy1 - y0f;
        int lx = min(max((int)x0f - x_org, 0), bwid - 2);
        int ly = min(max((int)y0f - y_org, 0), bhei - 2);
        const float w00 = (1.0f - dx) * (1.0f - dy);
        const float w10 = dx * (1.0f - dy);
        const float w01 = (1.0f - dx) * dy;
        const float w11 = dx * dy;
        const float4 t00 = tile[ly][lx];
        const float4 t10 = tile[ly][lx + 1];
        const float4 t01 = tile[ly + 1][lx];
        const float4 t11 = tile[ly + 1][lx + 1];
        r1[0] = t00.x * w00 + t10.x * w10 + t01.x * w01 + t11.x * w11;
        r1[1] = t00.y * w00 + t10.y * w10 + t01.y * w01 + t11.y * w11;
        r1[2] = t00.z * w00 + t10.z * w10 + t01.z * w01 + t11.z * w11;
    }

    float* ob = out + (((size_t)g * CHANS) * OUT_H + oy) * OUT_W + ox;
#pragma unroll
    for (int c = 0; c < CHANS; c++) {
        float2 rr = make_float2(r0[c], r1[c]);
        *reinterpret_cast<float2*>(ob + (size_t)c * (OUT_H * OUT_W)) = rr;
    }
}

extern "C" void kernel_launch(void* const* d_in, const int* in_sizes, int n_in,
                              void* d_out, int out_size) {
    const float* x     = (const float*)d_in[0];
    const float* boxes = (const float*)d_in[1];
    float* out         = (float*)d_out;

    dim3 grid(N_BOXES_TOTAL * NTX * NTY);   // 15360
    dim3 block(NTHREADS);
    rotated_roi_crop_v3<<<grid, block>>>(x, boxes, out);
}

// round 4
// speedup vs baseline: 1.1868x; 1.1868x over previous
#include <cuda_runtime.h>

// Rotated ROI cropper v4 = R2 structure + split-plane smem (float2 c0c1 + float c2)
//   x:     [8, 3, 1024, 1024] fp32
//   boxes: [8, 64, 5] fp32  (cx, cy, w, h, angle_deg)
//   out:   [512, 3, 48, 320] fp32
//
// Block = one 32x16 output tile of one box. Source bbox <= 38 px/side.
// Taps: 4x LDS.64 (channels 0,1) + 4x LDS.32 (channel 2) per pixel.

#define IMG_H 1024
#define IMG_W 1024
#define OUT_H 48
#define OUT_W 320
#define CHANS 3
#define N_BOXES_TOTAL 512
#define PLANE (IMG_H * IMG_W)

#define TILE_OX 32
#define TILE_OY 16
#define NTX (OUT_W / TILE_OX)   // 10
#define NTY (OUT_H / TILE_OY)   // 3

#define STILE  38
#define SPITCH 39               // odd pitch -> bank spread on diagonals

#define NTHREADS 256

__global__ __launch_bounds__(NTHREADS)
void rotated_roi_crop_v4(const float* __restrict__ x,
                         const float* __restrict__ boxes,
                         float* __restrict__ out) {
    __shared__ float2 tileAB[STILE][SPITCH];  // (c0, c1)
    __shared__ float  tileC [STILE][SPITCH];  // c2

    const int bid     = blockIdx.x;
    const int tx_tile = bid % NTX;
    const int ty_tile = (bid / NTX) % NTY;
    const int g       = bid / (NTX * NTY);

    // ---- box params (uniform broadcast) ----
    const float* bp = boxes + g * 5;
    const float cx  = bp[0];
    const float cy  = bp[1];
    const float bw  = bp[2];
    const float bh  = bp[3];
    const float ang = bp[4];

    const float theta = -ang * 0.017453292519943295f;
    float s_, c_;
    sincosf(theta, &s_, &c_);
    const float b = c_ * 0.5f;
    const float a = s_ * 0.5f;

    const float p0x = cx - a * bh - b * bw;
    const float p0y = cy + b * bh - a * bw;
    const float p1x = cx + a * bh - b * bw;
    const float p1y = cy - b * bh - a * bw;
    const float p2x = 2.0f * cx - p0x;
    const float p2y = 2.0f * cy - p0y;

    const float ex_x = p2x - p1x;   // source delta per unit u
    const float ex_y = p2y - p1y;
    const float ey_x = p0x - p1x;   // source delta per unit v
    const float ey_y = p0y - p1y;

    // ---- source bbox of this tile (4 affine corners) ----
    const float u0 = (float)(tx_tile * TILE_OX)               / (float)OUT_W;
    const float u1 = (float)(tx_tile * TILE_OX + TILE_OX - 1) / (float)OUT_W;
    const float v0 = (float)(ty_tile * TILE_OY)               / (float)OUT_H;
    const float v1 = (float)(ty_tile * TILE_OY + TILE_OY - 1) / (float)OUT_H;

    const float sxa = p1x + u0 * ex_x + v0 * ey_x;
    const float sxb = p1x + u1 * ex_x + v0 * ey_x;
    const float sxc = p1x + u0 * ex_x + v1 * ey_x;
    const float sxd = p1x + u1 * ex_x + v1 * ey_x;
    const float sya = p1y + u0 * ex_y + v0 * ey_y;
    const float syb = p1y + u1 * ex_y + v0 * ey_y;
    const float syc = p1y + u0 * ex_y + v1 * ey_y;
    const float syd = p1y + u1 * ex_y + v1 * ey_y;

    const int x_org = (int)floorf(fminf(fminf(sxa, sxb), fminf(sxc, sxd)));
    const int y_org = (int)floorf(fminf(fminf(sya, syb), fminf(syc, syd)));
    const int bwid = min((int)floorf(fmaxf(fmaxf(sxa, sxb), fmaxf(sxc, sxd))) + 2 - x_org, STILE);
    const int bhei = min((int)floorf(fmaxf(fmaxf(sya, syb), fmaxf(syc, syd))) + 2 - y_org, STILE);

    const int lane = threadIdx.x & 31;
    const int wrp  = threadIdx.x >> 5;   // 0..7

    // ---- staged load: warp-row-strided, no division ----
    const int batch = g >> 6;
    const float* img = x + (size_t)batch * CHANS * PLANE;
    const bool wide = (bwid > 32);

    for (int yy = wrp; yy < bhei; yy += 8) {
        const int gy = y_org + yy;
        const bool rok = ((unsigned)gy < IMG_H);
        const float* rp = img + (size_t)gy * IMG_W;

        {
            const int xx = lane;
            const int gx = x_org + xx;
            const bool ok = rok & ((unsigned)gx < IMG_W) & (xx < bwid);
            float c0 = 0.f, c1 = 0.f, c2 = 0.f;
            if (ok) {
                c0 = __ldg(rp + gx);
                c1 = __ldg(rp + gx + PLANE);
                c2 = __ldg(rp + gx + 2 * PLANE);
            }
            tileAB[yy][xx] = make_float2(c0, c1);
            tileC [yy][xx] = c2;
        }
        if (wide) {
            const int xx = 32 + lane;
            if (xx < STILE) {
                const int gx = x_org + xx;
                const bool ok = rok & ((unsigned)gx < IMG_W) & (xx < bwid);
                float c0 = 0.f, c1 = 0.f, c2 = 0.f;
                if (ok) {
                    c0 = __ldg(rp + gx);
                    c1 = __ldg(rp + gx + PLANE);
                    c2 = __ldg(rp + gx + 2 * PLANE);
                }
                tileAB[yy][xx] = make_float2(c0, c1);
                tileC [yy][xx] = c2;
            }
        }
    }
    __syncthreads();

    // ---- compute: warp = 32 contiguous output px; each thread 2 rows ----
    const int ox = tx_tile * TILE_OX + lane;
    const float u = (float)ox / (float)OUT_W;
    const float sxu = fmaf(u, ex_x, p1x);
    const float syu = fmaf(u, ex_y, p1y);

    const float2* __restrict__ tAB = &tileAB[0][0];
    const float*  __restrict__ tC  = &tileC[0][0];

    const int lxmax = bwid - 2;
    const int lymax = bhei - 2;

    float* ob0 = out + (((size_t)g * CHANS) * OUT_H) * OUT_W + ox;

#pragma unroll
    for (int r = 0; r < 2; r++) {
        const int oy = ty_tile * TILE_OY + wrp * 2 + r;
        const float v = (float)oy / (float)OUT_H;
        const float sx = fmaf(v, ey_x, sxu);
        const float sy = fmaf(v, ey_y, syu);

        const float x0f = floorf(sx);
        const float y0f = floorf(sy);
        const float dx = sx - x0f;
        const float dy = sy - y0f;

        int lx = min(max((int)x0f - x_org, 0), lxmax);
        int ly = min(max((int)y0f - y_org, 0), lymax);
        const int idx = ly * SPITCH + lx;

        const float omdx = 1.0f - dx;
        const float omdy = 1.0f - dy;
        const float w00 = omdx * omdy;
        const float w10 = dx * omdy;
        const float w01 = omdx * dy;
        const float w11 = dx * dy;

        const float2 t00 = tAB[idx];
        const float2 t10 = tAB[idx + 1];
        const float2 t01 = tAB[idx + SPITCH];
        const float2 t11 = tAB[idx + SPITCH + 1];
        const float  c00 = tC[idx];
        const float  c10 = tC[idx + 1];
        const float  c01 = tC[idx + SPITCH];
        const float  c11 = tC[idx + SPITCH + 1];

        const float r0 = fmaf(t11.x, w11, fmaf(t01.x, w01, fmaf(t10.x, w10, t00.x * w00)));
        const float r1 = fmaf(t11.y, w11, fmaf(t01.y, w01, fmaf(t10.y, w10, t00.y * w00)));
        const float r2 = fmaf(c11,   w11, fmaf(c01,   w01, fmaf(c10,   w10, c00   * w00)));

        float* ob = ob0 + (size_t)oy * OUT_W;
        ob[0]                       = r0;
        ob[OUT_H * OUT_W]           = r1;
        ob[2 * OUT_H * OUT_W]       = r2;
    }
}

extern "C" void kernel_launch(void* const* d_in, const int* in_sizes, int n_in,
                              void* d_out, int out_size) {
    const float* x     = (const float*)d_in[0];
    const float* boxes = (const float*)d_in[1];
    float* out         = (float*)d_out;

    dim3 grid(N_BOXES_TOTAL * NTX * NTY);   // 15360
    dim3 block(NTHREADS);
    rotated_roi_crop_v4<<<grid, block>>>(x, boxes, out);
}